// round 14
// baseline (speedup 1.0000x reference)
#include <cuda_runtime.h>
#include <cuda_fp16.h>
#include <math.h>
#include <cstdint>

#define BB 128
#define TT 512
#define II 512
#define HH 512
#define H3 1536
#define KK 512
#define NCTA 128

// ---------------- scratch (device globals: allocation-free) ----------------
__device__ __half g_x16[(size_t)BB * TT * II];            // x fp16 [B,T,I]
__device__ __half g_hb16[2][BB * HH];                     // h fp16 ping-pong
__device__ __half g_wxp16[H3 * II];                       // Wx fp16, gate-permuted
__device__ __half g_whp16[H3 * KK];                       // Wh fp16, gate-permuted
__device__ int g_bar_count;

// ================= PTX helpers (baseline ISA only: sm_80+) =================
#define CP_ASYNC16(dst, src) \
    asm volatile("cp.async.cg.shared.global [%0], [%1], 16;" \
                 :: "r"(dst), "l"(src) : "memory")
#define CP_COMMIT() asm volatile("cp.async.commit_group;" ::: "memory")
template <int N>
__device__ __forceinline__ void cp_wait() {
    asm volatile("cp.async.wait_group %0;" :: "n"(N) : "memory");
}

__device__ __forceinline__ uint32_t smem_to_u32(const void* p) {
    uint32_t a;
    asm("{ .reg .u64 t; cvta.to.shared.u64 t, %1; cvt.u32.u64 %0, t; }"
        : "=r"(a) : "l"(p));
    return a;
}

__device__ __forceinline__ void ldmatrix_x4(uint32_t& r0, uint32_t& r1,
                                            uint32_t& r2, uint32_t& r3,
                                            uint32_t addr) {
    asm volatile("ldmatrix.sync.aligned.m8n8.x4.shared.b16 {%0,%1,%2,%3}, [%4];"
                 : "=r"(r0), "=r"(r1), "=r"(r2), "=r"(r3) : "r"(addr));
}

__device__ __forceinline__ void ldmatrix_x2(uint32_t& r0, uint32_t& r1,
                                            uint32_t addr) {
    asm volatile("ldmatrix.sync.aligned.m8n8.x2.shared.b16 {%0,%1}, [%2];"
                 : "=r"(r0), "=r"(r1) : "r"(addr));
}

__device__ __forceinline__ void mma_f16(float* c, const uint32_t* a,
                                        const uint32_t* b) {
    asm volatile(
        "mma.sync.aligned.m16n8k16.row.col.f32.f16.f16.f32 "
        "{%0,%1,%2,%3}, {%4,%5,%6,%7}, {%8,%9}, {%0,%1,%2,%3};"
        : "+f"(c[0]), "+f"(c[1]), "+f"(c[2]), "+f"(c[3])
        : "r"(a[0]), "r"(a[1]), "r"(a[2]), "r"(a[3]), "r"(b[0]), "r"(b[1]));
}

// ---------------- small helpers ----------------
__global__ void reset_bar() { g_bar_count = 0; }

__global__ void copy_hfinal(const float* __restrict__ y, float* __restrict__ dst,
                            int n) {
    int i = blockIdx.x * blockDim.x + threadIdx.x;
    if (i >= n) return;
    int b = i >> 9;
    int u = i & 511;
    dst[i] = y[((size_t)b * TT + (TT - 1)) * HH + u];
}

// combined split: x->fp16, Wx/Wh->fp16 gate-permuted, h0->fp16
#define NX2 ((size_t)BB * TT * II / 2)
#define NW2 ((size_t)H3 * II / 2)
#define NH2 ((size_t)H3 * KK / 2)
#define NH0 ((size_t)BB * HH / 2)
__global__ void split_all(const float* __restrict__ x,
                          const float* __restrict__ wx,
                          const float* __restrict__ wh,
                          const float* __restrict__ h0,
                          __half* __restrict__ x16,
                          __half* __restrict__ wxp,
                          __half* __restrict__ whp,
                          __half* __restrict__ hb0) {
    size_t i = (size_t)blockIdx.x * blockDim.x + threadIdx.x;
    if (i < NX2) {
        float2 v = ((const float2*)x)[i];
        ((__half2*)x16)[i] = __halves2half2(__float2half_rn(v.x),
                                            __float2half_rn(v.y));
    } else if (i < NX2 + NW2 + NH2) {
        const float* src;
        __half* dst;
        size_t j;
        if (i < NX2 + NW2) { src = wx; dst = wxp; j = i - NX2; }
        else { src = wh; dst = whp; j = i - NX2 - NW2; }
        int g = (int)(j >> 8);            // row 0..1535
        int k2 = (int)(j & 255);          // half2 col index
        int gate = g >> 9;
        int u = g & 511;
        int prow = (u >> 3) * 24 + gate * 8 + (u & 7);   // gate-permuted row
        float2 v = ((const float2*)src)[j];
        ((__half2*)dst)[(size_t)prow * 256 + k2] =
            __halves2half2(__float2half_rn(v.x), __float2half_rn(v.y));
    } else if (i < NX2 + NW2 + NH2 + NH0) {
        size_t j = i - NX2 - NW2 - NH2;
        float2 v = ((const float2*)h0)[j];
        ((__half2*)hb0)[j] = __halves2half2(__float2half_rn(v.x),
                                            __float2half_rn(v.y));
    }
}

// ---------------- Fused persistent recurrence, x-mma OFF critical path ----
// 128 CTAs = 64 unit-groups x 2 batch-halves; CTA tile 64b x 24n; K=512 for
// both paths. 8 warps: wm = wid&3 (m16-tile), wk = wid>>2 (k16 parity).
// Loop: [accx(t) in regs] -> WAIT(t) -> stage h -> h-mma -> reduce -> gate,
// store h(t) -> ARRIVE -> stage_x(t+1) -> x-mma(t+1) (overlaps other CTAs'
// arrival skew; the next WAIT then returns immediately).
#define RSA 520
#define RSB 520
#define A_SZ (64 * RSA * 2)             // 66560
#define B_SZ (24 * RSB * 2)             // 24960
#define SM_AX 0
#define SM_AH A_SZ
#define SM_BWX (2 * A_SZ)
#define SM_BWH (2 * A_SZ + B_SZ)
#define SM_RED (2 * A_SZ + 2 * B_SZ)    // 183040
#define SMT (SM_RED + 4 * 32 * 17 * 4)  // 191744

__global__ void __launch_bounds__(256, 1) gru_fused(
    const __half* __restrict__ x16,
    const __half* __restrict__ wxp,
    const __half* __restrict__ whp,
    const float* __restrict__ bx,
    const float* __restrict__ h0,
    __half* __restrict__ hbuf,          // 2 x BB*HH fp16 ping-pong
    float* __restrict__ y) {
    extern __shared__ char smh[];
    const uint32_t sb = smem_to_u32(smh);

    const int tid = threadIdx.x;
    const int lane = tid & 31;
    const int wid = tid >> 5;
    const int wm = wid & 3;             // m16-tile 0..3
    const int wk = wid >> 2;            // k16 parity 0..1
    const int cta = blockIdx.x;
    const int ug = cta >> 1;            // unit group 0..63
    const int mh = cta & 1;             // batch half
    const int b0 = mh * 64;
    const int lrow = lane & 15;
    const int lcol8 = (lane >> 4) * 8;

    const int gr0 = b0 + wm * 16 + (lane >> 2);      // batches +0,+8
    const int gu0 = ug * 8 + (lane & 3) * 2;         // units +0,+1

    // reg-carried h_old and biases (gating warps only)
    float hold[2][2], bz[2], br[2], bn[2];
    if (wk == 0) {
#pragma unroll
        for (int rh = 0; rh < 2; rh++)
#pragma unroll
            for (int ui = 0; ui < 2; ui++)
                hold[rh][ui] = h0[(gr0 + rh * 8) * HH + gu0 + ui];
#pragma unroll
        for (int ui = 0; ui < 2; ui++) {
            bz[ui] = bx[gu0 + ui];
            br[ui] = bx[gu0 + ui + 512];
            bn[ui] = bx[gu0 + ui + 1024];
        }
    }

    // ---- stage resident permuted Wx + Wh tiles: rows [ug*24, +24) ----
    {
#pragma unroll
        for (int i = 0; i < 6; i++) {
            int c = tid + i * 256;            // 0..1535
            int row = c >> 6;                 // 0..23
            int seg = c & 63;
            CP_ASYNC16(sb + SM_BWX + (row * RSB + seg * 8) * 2,
                       (const void*)(wxp + (size_t)(ug * 24 + row) * II + seg * 8));
            CP_ASYNC16(sb + SM_BWH + (row * RSB + seg * 8) * 2,
                       (const void*)(whp + (size_t)(ug * 24 + row) * KK + seg * 8));
        }
        CP_COMMIT();
    }

    auto stage_x = [&](int t) {
#pragma unroll
        for (int i = 0; i < 16; i++) {
            int c = tid + i * 256;            // 0..4095
            int row = c >> 6;                 // 0..63
            int seg = c & 63;
            CP_ASYNC16(sb + SM_AX + (row * RSA + seg * 8) * 2,
                       (const void*)(x16 + ((size_t)(b0 + row) * TT + t) * II + seg * 8));
        }
        CP_COMMIT();
    };

    // one k16-step of mma on staged data (k16 = 2j + wk)
    auto do_k = [&](int j, float acc[3][4], uint32_t abase, uint32_t bbase) {
        const int k16 = 2 * j + wk;
        const uint32_t coloff = (k16 * 16 + lcol8) * 2;
        uint32_t a[4];
        ldmatrix_x4(a[0], a[1], a[2], a[3],
                    abase + (wm * 16 + lrow) * (RSA * 2) + coloff);
        uint32_t bh[3][2];
        {
            uint32_t r0, r1, r2, r3;
            ldmatrix_x4(r0, r1, r2, r3, bbase + lrow * (RSB * 2) + coloff);
            bh[0][0] = r0; bh[1][0] = r1; bh[0][1] = r2; bh[1][1] = r3;
            const uint32_t a2 = (16 + (lane & 7)) * (RSB * 2) +
                                (k16 * 16 + ((lane >> 3) & 1) * 8) * 2;
            ldmatrix_x2(bh[2][0], bh[2][1], bbase + a2);
        }
#pragma unroll
        for (int nt = 0; nt < 3; nt++) mma_f16(acc[nt], a, bh[nt]);
    };

    // ---- prologue: stage x(0), compute accx(0) ----
    float accx[3][4];
    stage_x(0);
    cp_wait<0>();                       // weights + x(0) staged
    __syncthreads();
#pragma unroll
    for (int j = 0; j < 3; j++)
#pragma unroll
        for (int q = 0; q < 4; q++) accx[j][q] = 0.f;
#pragma unroll
    for (int j = 0; j < 16; j++) do_k(j, accx, sb + SM_AX, sb + SM_BWX);

    for (int t = 0; t < TT; t++) {
        // ---- barrier WAIT: h(t-1) stores from all CTAs visible ----
        if (t > 0) {
            if (tid == 0) {
                const int target = NCTA * t;
                while (*((volatile int*)&g_bar_count) < target) { }
                __threadfence();               // acquire
            }
        }
        __syncthreads();

        // ---- stage A_h = h fp16 [64b x 512k] in 2 chunks ----
        const __half* hsrc = hbuf + (size_t)(t & 1) * (BB * HH);
#pragma unroll
        for (int ch = 0; ch < 2; ch++) {
#pragma unroll
            for (int i = 0; i < 8; i++) {
                int c = tid + i * 256;        // 0..2047
                int row = c >> 5;             // 0..63
                int seg = ch * 32 + (c & 31);
                CP_ASYNC16(sb + SM_AH + (row * RSA + seg * 8) * 2,
                           (const void*)(hsrc + (size_t)(b0 + row) * HH + seg * 8));
            }
            CP_COMMIT();
        }

        float acch[3][4];
#pragma unroll
        for (int j = 0; j < 3; j++)
#pragma unroll
            for (int q = 0; q < 4; q++) acch[j][q] = 0.f;

        cp_wait<1>();                   // h chunk 0 (k 0..255) ready
        __syncthreads();
#pragma unroll
        for (int j = 0; j < 8; j++) do_k(j, acch, sb + SM_AH, sb + SM_BWH);

        cp_wait<0>();                   // h chunk 1 ready
        __syncthreads();
#pragma unroll
        for (int j = 8; j < 16; j++) do_k(j, acch, sb + SM_AH, sb + SM_BWH);

        // ---- k-parity reduce: z,r merged; xn,hn kept separate (16 floats) --
        if (wk == 1) {
            float* rp = (float*)(smh + SM_RED) + (wm * 32 + lane) * 17;
#pragma unroll
            for (int q = 0; q < 4; q++) {
                rp[q]      = accx[0][q] + acch[0][q];  // z
                rp[4 + q]  = accx[1][q] + acch[1][q];  // r
                rp[8 + q]  = accx[2][q];               // xn
                rp[12 + q] = acch[2][q];               // hn
            }
        }
        __syncthreads();

        // ---- gating (wk==0): z/r/n register-local triplets + bias ----
        if (wk == 0) {
            const float* rp = (float*)(smh + SM_RED) + (wm * 32 + lane) * 17;
            float vz[4], vr[4], vxn[4], vhn[4];
#pragma unroll
            for (int q = 0; q < 4; q++) {
                vz[q]  = accx[0][q] + acch[0][q] + rp[q];
                vr[q]  = accx[1][q] + acch[1][q] + rp[4 + q];
                vxn[q] = accx[2][q] + rp[8 + q];
                vhn[q] = acch[2][q] + rp[12 + q];
            }
            __half* hdst = hbuf + (size_t)((t + 1) & 1) * (BB * HH);
#pragma unroll
            for (int rh = 0; rh < 2; rh++) {
#pragma unroll
                for (int ui = 0; ui < 2; ui++) {
                    const int q = rh * 2 + ui;
                    const int b = gr0 + rh * 8;
                    const int u = gu0 + ui;
                    float z = 1.f / (1.f + __expf(-(vz[q] + bz[ui])));
                    float r = 1.f / (1.f + __expf(-(vr[q] + br[ui])));
                    float n = tanhf(vxn[q] + bn[ui] + r * vhn[q]);
                    float hn = fmaf(z, hold[rh][ui] - n, n);
                    hold[rh][ui] = hn;
                    y[((size_t)b * TT + t) * HH + u] = hn;
                    hdst[b * HH + u] = __float2half_rn(hn);
                }
            }
        }
        __syncthreads();                 // h(t) stores issued block-wide

        // ---- barrier ARRIVE (release h(t) stores) ----
        if (tid == 0) {
            __threadfence();
            atomicAdd(&g_bar_count, 1);
        }

        // ---- off-critical-path: stage x(t+1) + x-mma(t+1) ----
        // Runs while other CTAs finish their step and arrive; the next WAIT
        // then returns ~immediately. SM_AX rewrite is safe: all reads of
        // accx(t)'s tile finished before the reduce-syncthreads above.
        if (t + 1 < TT) {
            stage_x(t + 1);
            cp_wait<0>();
            __syncthreads();
#pragma unroll
            for (int j = 0; j < 3; j++)
#pragma unroll
                for (int q = 0; q < 4; q++) accx[j][q] = 0.f;
#pragma unroll
            for (int j = 0; j < 16; j++) do_k(j, accx, sb + SM_AX, sb + SM_BWX);
        }
    }
}

// ---------------- launch ----------------
extern "C" void kernel_launch(void* const* d_in, const int* in_sizes, int n_in,
                              void* d_out, int out_size) {
    const float* x  = (const float*)d_in[0];  // [B,T,I]
    const float* h0 = (const float*)d_in[1];  // [B,H]
    const float* Wx = (const float*)d_in[2];  // [3H,I]
    const float* bx = (const float*)d_in[3];  // [3H]
    const float* Wh = (const float*)d_in[4];  // [3H,H]
    float* out = (float*)d_out;

    __half *x16, *wxp, *whp, *hbuf;
    cudaGetSymbolAddress((void**)&x16, g_x16);
    cudaGetSymbolAddress((void**)&wxp, g_wxp16);
    cudaGetSymbolAddress((void**)&whp, g_whp16);
    cudaGetSymbolAddress((void**)&hbuf, g_hb16);

    cudaFuncSetAttribute(gru_fused, cudaFuncAttributeMaxDynamicSharedMemorySize,
                         SMT);

    reset_bar<<<1, 1>>>();                                              // 0
    {
        size_t tot = NX2 + NW2 + NH2 + NH0;
        split_all<<<(unsigned)((tot + 255) / 256), 256>>>(              // 1
            x, Wx, Wh, h0, x16, wxp, whp, hbuf);
    }
    gru_fused<<<NCTA, 256, SMT>>>(x16, wxp, whp, bx, h0, hbuf, out);    // 2
    if (out_size >= (int)((size_t)BB * TT * HH + BB * HH)) {
        copy_hfinal<<<(BB * HH + 255) / 256, 256>>>(out, out + (size_t)BB * TT * HH,
                                                    BB * HH);           // 3
    }
}